// round 4
// baseline (speedup 1.0000x reference)
#include <cuda_runtime.h>
#include <cuda_bf16.h>
#include <cstdint>

#define D 128
#define NA 100000
#define NB 150000
#define NG 2000
#define NTOT (NA + NB + NG)      // 252000
#define MAXN NB
#define DEG_TOT 756000           // sum over rels of n_dst (= sum of n_src)
#define NE_TOT 1352000           // total edges over 9 relations
#define BN_EPS 1e-5f
#define SCAN_NB ((DEG_TOT + 1023) / 1024)   // 739

// ---------------- device scratch ----------------
__device__ int g_odeg[DEG_TOT];                   // per-(rel,src) out-degree
__device__ int g_ideg[DEG_TOT];                   // per-(rel,dst) in-degree
__device__ int g_offs[DEG_TOT];                   // exclusive scan of ideg (global CSR offsets)
__device__ int g_cursor[DEG_TOT];
__device__ int g_bsum[SCAN_NB];
__device__ int g_eidx[NE_TOT];                    // CSR: src index per edge slot
__device__ float g_ew[NE_TOT];                    // CSR: ns[src] per edge slot
__device__ float g_ns[DEG_TOT];
__device__ float g_nd[DEG_TOT];
__device__ float g_m[(size_t)MAXN * D];           // aggregated messages (written once, no zero)
__device__ float g_gout[(size_t)DEG_TOT * D];     // per-rel gout, dst-major offsets
__device__ float g_feat[(size_t)NTOT * D];        // layer-0 output
__device__ float g_stats[9 * 2 * D];              // per-rel col sum / sumsq
__device__ float g_scale[9 * D];
__device__ float g_shift[9 * D];
__device__ __nv_bfloat16 g_wh[18 * D * D];        // pre-split W hi (swizzled B-tile layout)
__device__ __nv_bfloat16 g_wl[18 * D * D];        // pre-split W lo

__device__ const int d_ndst[9] = {NB, NA, NG, NA, NG, NB, NA, NB, NG};

// ---------------- layout helpers ----------------
__device__ __forceinline__ uint32_t sw128(uint32_t o) { return o ^ ((o >> 3) & 0x70); }
// 128x128 bf16 tile as two [128 rows x 64 k] half-tiles (16KB each), 128B swizzled rows
__device__ __forceinline__ uint32_t toff128(uint32_t row, uint32_t k) {
    return ((k >> 6) << 14) + sw128(row * 128 + ((k & 63) << 1));
}

__device__ __forceinline__ uint32_t smem_u32(const void* p) {
    uint32_t a;
    asm("{ .reg .u64 t; cvta.to.shared.u64 t, %1; cvt.u32.u64 %0, t; }" : "=r"(a) : "l"(p));
    return a;
}

__device__ __forceinline__ void ldsm4(uint32_t& r0, uint32_t& r1, uint32_t& r2, uint32_t& r3,
                                      uint32_t addr) {
    asm volatile("ldmatrix.sync.aligned.m8n8.x4.shared.b16 {%0,%1,%2,%3}, [%4];"
                 : "=r"(r0), "=r"(r1), "=r"(r2), "=r"(r3) : "r"(addr));
}

__device__ __forceinline__ void mma_bf16(float* d, const uint32_t* a, uint32_t b0, uint32_t b1) {
    asm volatile(
        "mma.sync.aligned.m16n8k16.row.col.f32.bf16.bf16.f32 "
        "{%0,%1,%2,%3}, {%4,%5,%6,%7}, {%8,%9}, {%0,%1,%2,%3};"
        : "+f"(d[0]), "+f"(d[1]), "+f"(d[2]), "+f"(d[3])
        : "r"(a[0]), "r"(a[1]), "r"(a[2]), "r"(a[3]), "r"(b0), "r"(b1));
}

// ---------------- small kernels ----------------
__global__ void k_zero4(float4* p, int n4) {
    int i = blockIdx.x * blockDim.x + threadIdx.x;
    if (i < n4) p[i] = make_float4(0.f, 0.f, 0.f, 0.f);
}

__global__ void k_counti(const int* __restrict__ src, const int* __restrict__ dst,
                         int ne, int* __restrict__ od, int* __restrict__ id) {
    int e = blockIdx.x * blockDim.x + threadIdx.x;
    if (e < ne) {
        atomicAdd(&od[src[e]], 1);
        atomicAdd(&id[dst[e]], 1);
    }
}

__global__ void k_rsqrt_i(const int* __restrict__ c, float* __restrict__ o, int n) {
    int i = blockIdx.x * blockDim.x + threadIdx.x;
    if (i < n) {
        int v = c[i];
        o[i] = (v > 0) ? rsqrtf((float)v) : 0.f;
    }
}

// hierarchical exclusive scan: scan1 per-1024 block, scan2 over block sums, scan3 add back
__global__ void k_scan1(const int* __restrict__ in, int* __restrict__ out,
                        int* __restrict__ bsum, int n) {
    __shared__ int sh[1024];
    int gid = blockIdx.x * 1024 + threadIdx.x;
    int v = (gid < n) ? in[gid] : 0;
    sh[threadIdx.x] = v;
    __syncthreads();
#pragma unroll
    for (int s = 1; s < 1024; s <<= 1) {
        int t = (threadIdx.x >= s) ? sh[threadIdx.x - s] : 0;
        __syncthreads();
        sh[threadIdx.x] += t;
        __syncthreads();
    }
    if (gid < n) out[gid] = sh[threadIdx.x] - v;
    if (threadIdx.x == 1023) bsum[blockIdx.x] = sh[1023];
}

__global__ void k_scan2(int* __restrict__ bsum, int nb) {
    __shared__ int sh[1024];
    int v = (threadIdx.x < nb) ? bsum[threadIdx.x] : 0;
    sh[threadIdx.x] = v;
    __syncthreads();
#pragma unroll
    for (int s = 1; s < 1024; s <<= 1) {
        int t = (threadIdx.x >= s) ? sh[threadIdx.x - s] : 0;
        __syncthreads();
        sh[threadIdx.x] += t;
        __syncthreads();
    }
    if (threadIdx.x < nb) bsum[threadIdx.x] = sh[threadIdx.x] - v;
}

__global__ void k_scan3(int* __restrict__ out, const int* __restrict__ bsum, int n) {
    int gid = blockIdx.x * 1024 + threadIdx.x;
    if (gid < n) out[gid] += bsum[blockIdx.x];
}

// fill CSR slots: store (src, ns[src]) at offs[dst] + cursor++
__global__ void k_fill(const int* __restrict__ src, const int* __restrict__ dst,
                       const float* __restrict__ ns_rel, const int* __restrict__ offs_rel,
                       int* __restrict__ cur_rel, int ne) {
    int e = blockIdx.x * blockDim.x + threadIdx.x;
    if (e >= ne) return;
    int s = src[e];
    int d = dst[e];
    int pos = offs_rel[d] + atomicAdd(&cur_rel[d], 1);
    g_eidx[pos] = s;
    g_ew[pos] = ns_rel[s];
}

// split W (fp32 [18][k][n]) into bf16 hi/lo stored as B tile [n][k], swizzled
__global__ void k_wsplit(const float* __restrict__ W) {
    int rel = blockIdx.x;  // 0..17
    const float* w = W + (size_t)rel * D * D;
    char* wh = (char*)g_wh + (size_t)rel * D * D * 2;
    char* wl = (char*)g_wl + (size_t)rel * D * D * 2;
    for (int idx = threadIdx.x; idx < D * D; idx += blockDim.x) {
        int k = idx >> 7, n = idx & 127;
        float x = w[idx];
        __nv_bfloat16 h = __float2bfloat16(x);
        __nv_bfloat16 l = __float2bfloat16(x - __bfloat162float(h));
        uint32_t off = toff128(n, k);
        *(__nv_bfloat16*)(wh + off) = h;
        *(__nv_bfloat16*)(wl + off) = l;
    }
}

// CSR gather: one warp per dst row; m[row] = sum_e feat[eidx[e]] * ew[e] (single write, no atomics)
__global__ void k_gather(const float* __restrict__ feat, const int* __restrict__ offs,
                         const int* __restrict__ deg, const int* __restrict__ eidx,
                         const float* __restrict__ ew, float* __restrict__ m, int nrows) {
    int row = blockIdx.x * (blockDim.x >> 5) + (threadIdx.x >> 5);
    int lane = threadIdx.x & 31;
    if (row >= nrows) return;
    int o = offs[row];
    int dg = deg[row];
    float4 acc = make_float4(0.f, 0.f, 0.f, 0.f);
    int e = 0;
    // 2-deep software pipeline for MLP
    for (; e + 2 <= dg; e += 2) {
        int s0 = __ldg(eidx + o + e);
        int s1 = __ldg(eidx + o + e + 1);
        float w0 = __ldg(ew + o + e);
        float w1 = __ldg(ew + o + e + 1);
        float4 v0 = __ldg((const float4*)(feat + (size_t)s0 * D + lane * 4));
        float4 v1 = __ldg((const float4*)(feat + (size_t)s1 * D + lane * 4));
        acc.x += v0.x * w0 + v1.x * w1;
        acc.y += v0.y * w0 + v1.y * w1;
        acc.z += v0.z * w0 + v1.z * w1;
        acc.w += v0.w * w0 + v1.w * w1;
    }
    if (e < dg) {
        int s0 = __ldg(eidx + o + e);
        float w0 = __ldg(ew + o + e);
        float4 v0 = __ldg((const float4*)(feat + (size_t)s0 * D + lane * 4));
        acc.x += v0.x * w0;
        acc.y += v0.y * w0;
        acc.z += v0.z * w0;
        acc.w += v0.w * w0;
    }
    *(float4*)(m + (size_t)row * D + lane * 4) = acc;
}

// ---------------- mma.sync GEMM + fused epilogue ----------------
// out[gr] = (A[gr] @ W) * nd[gr] ; col sum/sumsq -> stats   (bias dropped: BN-invariant)
#define OFF_AHI  0
#define OFF_ALO  32768
#define OFF_BHI  65536
#define OFF_BLO  98304
#define OFF_STAT 131072
#define SMEM_DYN (131072 + 1024 + 1024)

__global__ __launch_bounds__(256, 1)
void k_gemm_mma(const float* __restrict__ A,
                const __nv_bfloat16* __restrict__ whi, const __nv_bfloat16* __restrict__ wlo,
                const float* __restrict__ nd,
                float* __restrict__ out, float* __restrict__ stats, int mrows) {
    extern __shared__ char smem_raw[];
    char* smem = (char*)((((uintptr_t)smem_raw) + 1023) & ~(uintptr_t)1023);
    uint32_t sa = smem_u32(smem);
    int tid = threadIdx.x;
    int lane = tid & 31;
    int wid = tid >> 5;
    int rowBase = blockIdx.x * 128;

    // B (pre-split, pre-swizzled) -> smem
    {
        const uint4* bh = (const uint4*)whi;
        const uint4* bl = (const uint4*)wlo;
        uint4* sh = (uint4*)(smem + OFF_BHI);
        uint4* sl = (uint4*)(smem + OFF_BLO);
#pragma unroll
        for (int i = 0; i < 8; i++) {
            sh[tid + i * 256] = __ldg(&bh[tid + i * 256]);
            sl[tid + i * 256] = __ldg(&bl[tid + i * 256]);
        }
    }
    ((float*)(smem + OFF_STAT))[tid] = 0.f;

    // A: fp32 -> bf16 hi/lo, swizzled. thread t: row t/2, k-half (t&1)*64
    {
        int row = tid >> 1;
        int gr = rowBase + row;
        int kh = (tid & 1) * 64;
        char* ah = smem + OFF_AHI;
        char* al = smem + OFF_ALO;
#pragma unroll
        for (int k = 0; k < 64; k += 4) {
            float4 v = make_float4(0.f, 0.f, 0.f, 0.f);
            if (gr < mrows) v = *(const float4*)(A + (size_t)gr * D + kh + k);
            __nv_bfloat16 hx = __float2bfloat16(v.x), hy = __float2bfloat16(v.y);
            __nv_bfloat16 hz = __float2bfloat16(v.z), hw = __float2bfloat16(v.w);
            __nv_bfloat162 h0; h0.x = hx; h0.y = hy;
            __nv_bfloat162 h1; h1.x = hz; h1.y = hw;
            __nv_bfloat162 l0, l1;
            l0.x = __float2bfloat16(v.x - __bfloat162float(hx));
            l0.y = __float2bfloat16(v.y - __bfloat162float(hy));
            l1.x = __float2bfloat16(v.z - __bfloat162float(hz));
            l1.y = __float2bfloat16(v.w - __bfloat162float(hw));
            uint32_t o0 = toff128(row, kh + k);
            uint32_t o1 = toff128(row, kh + k + 2);
            *(__nv_bfloat162*)(ah + o0) = h0;
            *(__nv_bfloat162*)(ah + o1) = h1;
            *(__nv_bfloat162*)(al + o0) = l0;
            *(__nv_bfloat162*)(al + o1) = l1;
        }
    }
    __syncthreads();

    // warp w: rows [w*16, w*16+16), all 128 cols
    float acc[16][4];
#pragma unroll
    for (int t = 0; t < 16; t++)
#pragma unroll
        for (int j = 0; j < 4; j++) acc[t][j] = 0.f;

    int m0 = wid * 16;
    uint32_t rowA = m0 + (lane & 15);
    uint32_t kA = (lane >> 4) << 3;
    uint32_t rowB = (lane & 7) + ((lane >> 4) << 3);
    uint32_t kB = ((lane >> 3) & 1) << 3;

    const uint32_t abase[3] = {sa + OFF_AHI, sa + OFF_AHI, sa + OFF_ALO};
    const uint32_t bbase[3] = {sa + OFF_BHI, sa + OFF_BLO, sa + OFF_BHI};

#pragma unroll
    for (int s = 0; s < 3; s++) {
        uint32_t ab = abase[s];
        uint32_t bb = bbase[s];
#pragma unroll
        for (int k0 = 0; k0 < 128; k0 += 16) {
            uint32_t a[4];
            ldsm4(a[0], a[1], a[2], a[3], ab + toff128(rowA, k0 + kA));
#pragma unroll
            for (int nn = 0; nn < 8; nn++) {
                uint32_t b0, b1, b2, b3;
                ldsm4(b0, b1, b2, b3, bb + toff128(nn * 16 + rowB, k0 + kB));
                mma_bf16(acc[2 * nn], a, b0, b1);
                mma_bf16(acc[2 * nn + 1], a, b2, b3);
            }
        }
    }

    // epilogue: thread holds rows (m0+quad, m0+quad+8), cols 8t+cp, 8t+cp+1
    int quad = lane >> 2;
    int cp = (lane & 3) * 2;
    int gr0 = rowBase + m0 + quad;
    int gr1 = gr0 + 8;
    bool v0 = gr0 < mrows, v1 = gr1 < mrows;
    float nd0 = v0 ? nd[gr0] : 0.f;
    float nd1 = v1 ? nd[gr1] : 0.f;
    float* sstat = (float*)(smem + OFF_STAT);

#pragma unroll
    for (int t = 0; t < 16; t++) {
        int c = t * 8 + cp;
        float x0 = acc[t][0] * nd0, x1 = acc[t][1] * nd0;
        float y0 = acc[t][2] * nd1, y1 = acc[t][3] * nd1;
        if (v0) *(float2*)(out + (size_t)gr0 * D + c) = make_float2(x0, x1);
        if (v1) *(float2*)(out + (size_t)gr1 * D + c) = make_float2(y0, y1);
        float s0 = (v0 ? x0 : 0.f) + (v1 ? y0 : 0.f);
        float s1 = (v0 ? x1 : 0.f) + (v1 ? y1 : 0.f);
        float q0 = (v0 ? x0 * x0 : 0.f) + (v1 ? y0 * y0 : 0.f);
        float q1 = (v0 ? x1 * x1 : 0.f) + (v1 ? y1 * y1 : 0.f);
#pragma unroll
        for (int S = 4; S <= 16; S <<= 1) {
            s0 += __shfl_xor_sync(0xffffffffu, s0, S);
            s1 += __shfl_xor_sync(0xffffffffu, s1, S);
            q0 += __shfl_xor_sync(0xffffffffu, q0, S);
            q1 += __shfl_xor_sync(0xffffffffu, q1, S);
        }
        if (lane < 4) {
            atomicAdd(&sstat[c], s0);
            atomicAdd(&sstat[c + 1], s1);
            atomicAdd(&sstat[128 + c], q0);
            atomicAdd(&sstat[128 + c + 1], q1);
        }
    }
    __syncthreads();
    atomicAdd(&stats[tid], sstat[tid]);
}

// per-rel BN scale/shift from stats
__global__ void k_finalize9(const float* __restrict__ gammaL, const float* __restrict__ betaL) {
    int r = blockIdx.x;
    int c = threadIdx.x;
    float n = (float)d_ndst[r];
    float mu = g_stats[r * 256 + c] / n;
    float var = g_stats[r * 256 + 128 + c] / n - mu * mu;
    float inv = rsqrtf(var + BN_EPS);
    float sc = inv * gammaL[r * D + c];
    g_scale[r * D + c] = sc;
    g_shift[r * D + c] = betaL[r * D + c] - mu * sc;
}

// fused: out = sum_{3 rels} gout_s * scale_s + shift_s (+ resid)
__global__ void k_fuse3(const float4* __restrict__ g0, const float4* __restrict__ g1,
                        const float4* __restrict__ g2,
                        const float* __restrict__ sc0, const float* __restrict__ sc1,
                        const float* __restrict__ sc2,
                        const float* __restrict__ sh0, const float* __restrict__ sh1,
                        const float* __restrict__ sh2,
                        const float4* __restrict__ resid, float4* __restrict__ out, int n) {
    int i = blockIdx.x * blockDim.x + threadIdx.x;
    int total = n * 32;
    if (i >= total) return;
    int c = (i & 31) * 4;
    float4 a = g0[i], b = g1[i], g = g2[i];
    float4 o;
    o.x = a.x * sc0[c + 0] + b.x * sc1[c + 0] + g.x * sc2[c + 0] + sh0[c + 0] + sh1[c + 0] + sh2[c + 0];
    o.y = a.y * sc0[c + 1] + b.y * sc1[c + 1] + g.y * sc2[c + 1] + sh0[c + 1] + sh1[c + 1] + sh2[c + 1];
    o.z = a.z * sc0[c + 2] + b.z * sc1[c + 2] + g.z * sc2[c + 2] + sh0[c + 2] + sh1[c + 2] + sh2[c + 2];
    o.w = a.w * sc0[c + 3] + b.w * sc1[c + 3] + g.w * sc2[c + 3] + sh0[c + 3] + sh1[c + 3] + sh2[c + 3];
    if (resid) {
        float4 rr = resid[i];
        o.x += rr.x; o.y += rr.y; o.z += rr.z; o.w += rr.w;
    }
    out[i] = o;
}

// ---------------- host orchestration ----------------
static inline int cdiv(int a, int b) { return (a + b - 1) / b; }

extern "C" void kernel_launch(void* const* d_in, const int* in_sizes, int n_in,
                              void* d_out, int out_size) {
    const float* fa = (const float*)d_in[0];
    const float* fb = (const float*)d_in[1];
    const float* fg = (const float*)d_in[2];
    const float* W = (const float*)d_in[3];
    const float* gamma = (const float*)d_in[5];
    const float* beta = (const float*)d_in[6];
    const int* esrc[9];
    const int* edst[9];
    for (int r = 0; r < 9; r++) {
        esrc[r] = (const int*)d_in[7 + 2 * r];
        edst[r] = (const int*)d_in[8 + 2 * r];
    }

    static const int rel_st[9] = {0, 1, 0, 2, 1, 2, 0, 1, 2};
    static const int rel_dt[9] = {1, 0, 2, 0, 2, 1, 0, 1, 2};
    static const int rel_ne[9] = {300000, 300000, 100000, 100000,
                                  150000, 150000, 100000, 150000, 2000};
    static const int ntype[3] = {NA, NB, NG};
    static const int toff[3] = {0, NA, NA + NB};
    static const int dt_rels[3][3] = {{1, 3, 6}, {0, 5, 7}, {2, 4, 8}};

    int soff[9], doff[9];
    {
        int s = 0, d = 0;
        for (int r = 0; r < 9; r++) {
            soff[r] = s; s += ntype[rel_st[r]];
            doff[r] = d; d += ntype[rel_dt[r]];
        }
    }

    int *p_odeg, *p_ideg, *p_offs, *p_cursor, *p_bsum;
    float *p_ns, *p_nd, *p_m, *p_gout, *p_feat, *p_stats, *p_scale, *p_shift;
    int* p_eidx; float* p_ew;
    __nv_bfloat16 *p_wh, *p_wl;
    cudaGetSymbolAddress((void**)&p_odeg, g_odeg);
    cudaGetSymbolAddress((void**)&p_ideg, g_ideg);
    cudaGetSymbolAddress((void**)&p_offs, g_offs);
    cudaGetSymbolAddress((void**)&p_cursor, g_cursor);
    cudaGetSymbolAddress((void**)&p_bsum, g_bsum);
    cudaGetSymbolAddress((void**)&p_eidx, g_eidx);
    cudaGetSymbolAddress((void**)&p_ew, g_ew);
    cudaGetSymbolAddress((void**)&p_ns, g_ns);
    cudaGetSymbolAddress((void**)&p_nd, g_nd);
    cudaGetSymbolAddress((void**)&p_m, g_m);
    cudaGetSymbolAddress((void**)&p_gout, g_gout);
    cudaGetSymbolAddress((void**)&p_feat, g_feat);
    cudaGetSymbolAddress((void**)&p_stats, g_stats);
    cudaGetSymbolAddress((void**)&p_scale, g_scale);
    cudaGetSymbolAddress((void**)&p_shift, g_shift);
    cudaGetSymbolAddress((void**)&p_wh, g_wh);
    cudaGetSymbolAddress((void**)&p_wl, g_wl);

    cudaFuncSetAttribute(k_gemm_mma, cudaFuncAttributeMaxDynamicSharedMemorySize, SMEM_DYN);

    const int TB = 256;

    // ---- degrees (int) ----
    k_zero4<<<cdiv(DEG_TOT / 4, TB), TB>>>((float4*)p_odeg, DEG_TOT / 4);
    k_zero4<<<cdiv(DEG_TOT / 4, TB), TB>>>((float4*)p_ideg, DEG_TOT / 4);
    k_zero4<<<cdiv(DEG_TOT / 4, TB), TB>>>((float4*)p_cursor, DEG_TOT / 4);
    for (int r = 0; r < 9; r++)
        k_counti<<<cdiv(rel_ne[r], TB), TB>>>(esrc[r], edst[r], rel_ne[r],
                                              p_odeg + soff[r], p_ideg + doff[r]);
    k_rsqrt_i<<<cdiv(DEG_TOT, TB), TB>>>(p_odeg, p_ns, DEG_TOT);
    k_rsqrt_i<<<cdiv(DEG_TOT, TB), TB>>>(p_ideg, p_nd, DEG_TOT);

    // ---- CSR build (once; topology shared by both layers) ----
    k_scan1<<<SCAN_NB, 1024>>>(p_ideg, p_offs, p_bsum, DEG_TOT);
    k_scan2<<<1, 1024>>>(p_bsum, SCAN_NB);
    k_scan3<<<SCAN_NB, 1024>>>(p_offs, p_bsum, DEG_TOT);
    for (int r = 0; r < 9; r++)
        k_fill<<<cdiv(rel_ne[r], TB), TB>>>(esrc[r], edst[r], p_ns + soff[r],
                                            p_offs + doff[r], p_cursor + doff[r], rel_ne[r]);

    // pre-split weights (hi/lo bf16, swizzled B-tile layout)
    k_wsplit<<<18, 256>>>(W);

    const float* layer_feat[3];
    for (int l = 0; l < 2; l++) {
        if (l == 0) {
            layer_feat[0] = fa; layer_feat[1] = fb; layer_feat[2] = fg;
        } else {
            layer_feat[0] = p_feat;
            layer_feat[1] = p_feat + (size_t)NA * D;
            layer_feat[2] = p_feat + (size_t)(NA + NB) * D;
        }

        k_zero4<<<cdiv(9 * 256 / 4, TB), TB>>>((float4*)p_stats, 9 * 256 / 4);

        for (int r = 0; r < 9; r++) {
            int ndst = ntype[rel_dt[r]];
            k_gather<<<cdiv(ndst, TB / 32), TB>>>(layer_feat[rel_st[r]],
                                                  p_offs + doff[r], p_ideg + doff[r],
                                                  p_eidx, p_ew, p_m, ndst);
            int lr = l * 9 + r;
            k_gemm_mma<<<cdiv(ndst, 128), 256, SMEM_DYN>>>(
                p_m, p_wh + (size_t)lr * D * D, p_wl + (size_t)lr * D * D,
                p_nd + doff[r],
                p_gout + (size_t)doff[r] * D, p_stats + r * 256, ndst);
        }

        k_finalize9<<<9, 128>>>(gamma + (size_t)l * 9 * D, beta + (size_t)l * 9 * D);

        const float* resid_t[3] = {fa, fb, fg};
        for (int t = 0; t < 3; t++) {
            int n = ntype[t];
            const int* rl = dt_rels[t];
            float* outp = (l == 0) ? (p_feat + (size_t)toff[t] * D)
                                   : ((float*)d_out + (size_t)toff[t] * D);
            k_fuse3<<<cdiv(n * 32, TB), TB>>>(
                (const float4*)(p_gout + (size_t)doff[rl[0]] * D),
                (const float4*)(p_gout + (size_t)doff[rl[1]] * D),
                (const float4*)(p_gout + (size_t)doff[rl[2]] * D),
                p_scale + rl[0] * D, p_scale + rl[1] * D, p_scale + rl[2] * D,
                p_shift + rl[0] * D, p_shift + rl[1] * D, p_shift + rl[2] * D,
                (l == 0) ? nullptr : (const float4*)resid_t[t],
                (float4*)outp, n);
        }
    }
}